// round 1
// baseline (speedup 1.0000x reference)
#include <cuda_runtime.h>
#include <math.h>
#include <stdint.h>

#define Bb   32
#define Ss   2048
#define Hh   256
#define G4   1024
#define Ll   2
#define NCTA 128

// ---------------- device scratch (allocation-free: module globals) ----------------
__device__ float g_xp[(size_t)Bb * Ss * G4];   // 256 MB: per-layer input projection (+both biases)
__device__ float g_y0[(size_t)Bb * Ss * Hh];   // 64 MB: layer-0 output sequence
__device__ float g_h[2][Bb * Hh];              // double-buffered hidden state
__device__ volatile unsigned g_flag[NCTA];     // per-CTA barrier generation flags

// ---------------- f32x2 packed-FMA helpers (sm_103a) ----------------
typedef unsigned long long ull;
__device__ __forceinline__ ull pack2(float lo, float hi) {
    ull r; asm("mov.b64 %0,{%1,%2};" : "=l"(r) : "f"(lo), "f"(hi)); return r;
}
__device__ __forceinline__ void unpack2(ull v, float& lo, float& hi) {
    asm("mov.b64 {%0,%1},%2;" : "=f"(lo), "=f"(hi) : "l"(v));
}
__device__ __forceinline__ void fma2(ull& acc, ull a, ull b) {
    asm("fma.rn.f32x2 %0,%1,%2,%0;" : "+l"(acc) : "l"(a), "l"(b));
}

__device__ __forceinline__ float sigmoidf_(float x) { return 1.0f / (1.0f + expf(-x)); }

// ---------------- init: zero h double-buffer and barrier flags ----------------
__global__ void zero_state() {
    int i = blockIdx.x * blockDim.x + threadIdx.x;
    if (i < 2 * Bb * Hh) ((float*)g_h)[i] = 0.0f;
    if (i < NCTA) g_flag[i] = 0u;
}

// ---------------- xp GEMM: out[m,g] = X[m,:] . W[g,:] + (bi[g]+bh[g]) ----------------
// X: [M=B*S, K=256] row-major ; W: [1024, 256] row-major ; out = g_xp [M,1024]
// Tile BM=64, BN=128, BK=32; 256 threads; 4x8 microtile via f32x2.
__global__ __launch_bounds__(256) void gemm_xp(const float* __restrict__ xin,
                                               const float* __restrict__ Wih,
                                               const float* __restrict__ bih,
                                               const float* __restrict__ bhh,
                                               int layer)
{
    const float* X  = layer ? g_y0 : xin;
    const float* W  = Wih + (size_t)layer * G4 * Hh;
    const float* b1 = bih + layer * G4;
    const float* b2 = bhh + layer * G4;

    __shared__ float As[32][68];
    __shared__ float Bs[32][132];

    const int tid = threadIdx.x;
    const int tx = tid & 15, ty = tid >> 4;
    const int m0 = blockIdx.y * 64;
    const int n0 = blockIdx.x * 128;

    ull acc[4][4];
#pragma unroll
    for (int i = 0; i < 4; i++)
#pragma unroll
        for (int j = 0; j < 4; j++) acc[i][j] = 0ull;

    for (int k0 = 0; k0 < Hh; k0 += 32) {
        // load A tile (64 x 32) : 512 float4
#pragma unroll
        for (int r = 0; r < 2; r++) {
            int i = tid + r * 256;
            int row = i >> 3, kq = i & 7;
            float4 v = *(const float4*)&X[(size_t)(m0 + row) * Hh + k0 + kq * 4];
            As[kq * 4 + 0][row] = v.x; As[kq * 4 + 1][row] = v.y;
            As[kq * 4 + 2][row] = v.z; As[kq * 4 + 3][row] = v.w;
        }
        // load B tile (128 x 32) : 1024 float4
#pragma unroll
        for (int r = 0; r < 4; r++) {
            int i = tid + r * 256;
            int row = i >> 3, kq = i & 7;
            float4 v = *(const float4*)&W[(size_t)(n0 + row) * Hh + k0 + kq * 4];
            Bs[kq * 4 + 0][row] = v.x; Bs[kq * 4 + 1][row] = v.y;
            Bs[kq * 4 + 2][row] = v.z; Bs[kq * 4 + 3][row] = v.w;
        }
        __syncthreads();

#pragma unroll
        for (int kk = 0; kk < 32; kk++) {
            float4 a4 = *(const float4*)&As[kk][ty * 4];
            ull aa0 = pack2(a4.x, a4.x), aa1 = pack2(a4.y, a4.y);
            ull aa2 = pack2(a4.z, a4.z), aa3 = pack2(a4.w, a4.w);
            ulonglong2 bA = *(const ulonglong2*)&Bs[kk][tx * 4];
            ulonglong2 bB = *(const ulonglong2*)&Bs[kk][64 + tx * 4];
            fma2(acc[0][0], aa0, bA.x); fma2(acc[0][1], aa0, bA.y);
            fma2(acc[0][2], aa0, bB.x); fma2(acc[0][3], aa0, bB.y);
            fma2(acc[1][0], aa1, bA.x); fma2(acc[1][1], aa1, bA.y);
            fma2(acc[1][2], aa1, bB.x); fma2(acc[1][3], aa1, bB.y);
            fma2(acc[2][0], aa2, bA.x); fma2(acc[2][1], aa2, bA.y);
            fma2(acc[2][2], aa2, bB.x); fma2(acc[2][3], aa2, bB.y);
            fma2(acc[3][0], aa3, bA.x); fma2(acc[3][1], aa3, bA.y);
            fma2(acc[3][2], aa3, bB.x); fma2(acc[3][3], aa3, bB.y);
        }
        __syncthreads();
    }

    const int n1 = n0 + tx * 4;
    const int n2 = n0 + 64 + tx * 4;
    float4 bb1 = *(const float4*)&b1[n1];
    float4 bc1 = *(const float4*)&b2[n1];
    float4 bb2 = *(const float4*)&b1[n2];
    float4 bc2 = *(const float4*)&b2[n2];
    bb1.x += bc1.x; bb1.y += bc1.y; bb1.z += bc1.z; bb1.w += bc1.w;
    bb2.x += bc2.x; bb2.y += bc2.y; bb2.z += bc2.z; bb2.w += bc2.w;

#pragma unroll
    for (int i = 0; i < 4; i++) {
        float4 o1, o2;
        unpack2(acc[i][0], o1.x, o1.y);
        unpack2(acc[i][1], o1.z, o1.w);
        unpack2(acc[i][2], o2.x, o2.y);
        unpack2(acc[i][3], o2.z, o2.w);
        o1.x += bb1.x; o1.y += bb1.y; o1.z += bb1.z; o1.w += bb1.w;
        o2.x += bb2.x; o2.y += bb2.y; o2.z += bb2.z; o2.w += bb2.w;
        int m = m0 + ty * 4 + i;
        *(float4*)&g_xp[(size_t)m * G4 + n1] = o1;
        *(float4*)&g_xp[(size_t)m * G4 + n2] = o2;
    }
}

// ---------------- persistent LSTM recurrence (one layer) ----------------
// 128 CTAs x 256 threads. CTA j owns h-indices {2j, 2j+1} (8 gate rows) for all 32 batches.
// h double-buffered in global (L2-resident, __ldcg); c lives in SMEM (CTA-private).
// Global barrier: per-CTA generation flags (no single-address atomic contention).
__global__ __launch_bounds__(256, 1) void lstm_rec(const float* __restrict__ Whh,
                                                   float* __restrict__ yout,
                                                   float* __restrict__ hT,
                                                   float* __restrict__ cT,
                                                   int layer)
{
    __shared__ float w_s[8][260];
    __shared__ float h_s[Bb][260];
    __shared__ float red[8][33];
    __shared__ float c_s[64];

    const int tid = threadIdx.x;
    const int j   = blockIdx.x;
    const int n0  = j * 2;

    const float* W = Whh + (size_t)layer * G4 * Hh;
    float* y = layer ? yout : g_y0;

    // load the 8 gate rows this CTA owns (gates i,f,g,o at rows gate*256 + n0 + nl)
    for (int i = tid; i < 8 * Hh; i += 256) {
        int sub = i >> 8, k = i & 255;
        int gate = sub >> 1, nl = sub & 1;
        w_s[sub][k] = W[(size_t)(gate * 256 + n0 + nl) * Hh + k];
    }
    if (tid < 64) c_s[tid] = 0.0f;
    __syncthreads();

    const int b   = tid >> 3;
    const int sub = tid & 7;
    const int gate = sub >> 1, nl = sub & 1;
    const size_t xp_base = (size_t)b * Ss * G4 + (size_t)(gate * 256 + n0 + nl);

    for (int t = 0; t < Ss; t++) {
        // issue xp load early (DRAM/L2 latency overlaps h staging)
        float xpv = __ldg(&g_xp[xp_base + (size_t)t * G4]);

        // stage h (32 x 256) into SMEM, bypassing L1 (cross-SM producer)
        const float4* hg = (const float4*)&g_h[t & 1][0];
        for (int i = tid; i < (Bb * Hh) / 4; i += 256) {
            float4 v = __ldcg(&hg[i]);
            int r = i >> 6, c = (i & 63) * 4;
            *(float4*)&h_s[r][c] = v;
        }
        __syncthreads();

        // dot: acc = h[b,:] . w_s[sub,:]  (K = 256, f32x2, conflict-free LDS.128)
        const ulonglong2* h2 = (const ulonglong2*)&h_s[b][0];
        const ulonglong2* w2 = (const ulonglong2*)&w_s[sub][0];
        ull a0 = 0ull, a1 = 0ull, a2 = 0ull, a3 = 0ull;
#pragma unroll
        for (int k = 0; k < 64; k += 2) {
            ulonglong2 hv = h2[k],     wv = w2[k];
            ulonglong2 hw = h2[k + 1], ww = w2[k + 1];
            fma2(a0, hv.x, wv.x); fma2(a1, hv.y, wv.y);
            fma2(a2, hw.x, ww.x); fma2(a3, hw.y, ww.y);
        }
        float x0, x1, x2, x3, x4, x5, x6, x7;
        unpack2(a0, x0, x1); unpack2(a1, x2, x3);
        unpack2(a2, x4, x5); unpack2(a3, x6, x7);
        red[sub][b] = ((x0 + x4) + (x1 + x5)) + ((x2 + x6) + (x3 + x7)) + xpv;
        __syncthreads();

        // elementwise LSTM cell update for the 64 (b, n) pairs this CTA owns
        if (tid < 64) {
            int bb = tid & 31, nn = tid >> 5;
            float iv = red[0 + nn][bb];
            float fv = red[2 + nn][bb];
            float gv = red[4 + nn][bb];
            float ov = red[6 + nn][bb];
            float ig = sigmoidf_(iv);
            float fg = sigmoidf_(fv);
            float og = sigmoidf_(ov);
            float c  = fg * c_s[tid] + ig * tanhf(gv);
            float h  = og * tanhf(c);
            c_s[tid] = c;
            int n = n0 + nn;
            g_h[(t + 1) & 1][bb * Hh + n] = h;
            y[(size_t)bb * Ss * Hh + (size_t)t * Hh + n] = h;
            if (t == Ss - 1) { hT[bb * Hh + n] = h; cT[bb * Hh + n] = c; }
        }
        __threadfence();   // release h writes gpu-wide before flagging
        __syncthreads();

        // global barrier: per-CTA monotonic generation flags
        if (tid == 0) g_flag[j] = (unsigned)(t + 1);
        if (tid < NCTA) {
            unsigned tgt = (unsigned)(t + 1);
            while (g_flag[tid] < tgt) { __nanosleep(40); }
        }
        __syncthreads();
    }
}

// ---------------- launch ----------------
extern "C" void kernel_launch(void* const* d_in, const int* in_sizes, int n_in,
                              void* d_out, int out_size)
{
    (void)in_sizes; (void)n_in; (void)out_size;
    const float* x    = (const float*)d_in[0];   // [B,S,H]
    const float* Wih  = (const float*)d_in[1];   // [L,4H,H]
    const float* bih  = (const float*)d_in[2];   // [L,4H]
    const float* Whh  = (const float*)d_in[3];   // [L,4H,H]
    const float* bhh  = (const float*)d_in[4];   // [L,4H]

    float* out = (float*)d_out;
    float* y_x = out;                                   // [B,S,H]
    float* hT  = out + (size_t)Bb * Ss * Hh;            // [L,B,H]
    float* cT  = hT + (size_t)Ll * Bb * Hh;             // [L,B,H]

    dim3 ggrid(G4 / 128, (Bb * Ss) / 64);

    for (int layer = 0; layer < Ll; layer++) {
        zero_state<<<64, 256>>>();
        gemm_xp<<<ggrid, 256>>>(x, Wih, bih, bhh, layer);
        lstm_rec<<<NCTA, 256>>>(Whh, y_x,
                                hT + (size_t)layer * Bb * Hh,
                                cT + (size_t)layer * Bb * Hh,
                                layer);
    }
}

// round 2
// speedup vs baseline: 5.9457x; 5.9457x over previous
#include <cuda_runtime.h>
#include <math.h>
#include <stdint.h>

#define Bb   32
#define Ss   2048
#define Hh   256
#define G4   1024
#define Ll   2
#define CL   4          // CTAs per cluster (one batch per cluster)
#define NCTA (Bb * CL)  // 128

// ---------------- device scratch (allocation-free: module globals) ----------------
__device__ float g_xp[(size_t)Bb * Ss * G4];   // 256 MB: per-layer input projection (+both biases)
__device__ float g_y0[(size_t)Bb * Ss * Hh];   // 64 MB: layer-0 output sequence

// ---------------- helpers ----------------
typedef unsigned long long ull;
__device__ __forceinline__ ull pack2(float lo, float hi) {
    ull r; asm("mov.b64 %0,{%1,%2};" : "=l"(r) : "f"(lo), "f"(hi)); return r;
}
__device__ __forceinline__ void unpack2(ull v, float& lo, float& hi) {
    asm("mov.b64 {%0,%1},%2;" : "=f"(lo), "=f"(hi) : "l"(v));
}
__device__ __forceinline__ void fma2(ull& acc, ull a, ull b) {
    asm("fma.rn.f32x2 %0,%1,%2,%0;" : "+l"(acc) : "l"(a), "l"(b));
}
// pack two fp32 into bf16x2: lo -> bits[15:0], hi -> bits[31:16]
__device__ __forceinline__ unsigned pack_bf16x2(float lo, float hi) {
    unsigned d;
    asm("cvt.rn.bf16x2.f32 %0, %1, %2;" : "=r"(d) : "f"(hi), "f"(lo));
    return d;
}
// expand bf16x2 -> packed f32x2 (2 ALU ops; reg pair fused by allocator)
__device__ __forceinline__ ull expand_bf16x2(unsigned w) {
    unsigned lo, hi;
    asm("shl.b32 %0, %1, 16;" : "=r"(lo) : "r"(w));
    asm("and.b32 %0, %1, 0xFFFF0000;" : "=r"(hi) : "r"(w));
    ull r; asm("mov.b64 %0,{%1,%2};" : "=l"(r) : "r"(lo), "r"(hi));
    return r;
}
__device__ __forceinline__ float tanh_f(float x) {
    float y; asm("tanh.approx.f32 %0,%1;" : "=f"(y) : "f"(x)); return y;
}
__device__ __forceinline__ float sig_f(float x) {
    return fmaf(0.5f, tanh_f(0.5f * x), 0.5f);
}
__device__ __forceinline__ uint32_t smem_u32(const void* p) {
    uint32_t a;
    asm("{ .reg .u64 t; cvta.to.shared.u64 t, %1; cvt.u32.u64 %0, t; }" : "=r"(a) : "l"(p));
    return a;
}
__device__ __forceinline__ void st_cluster_f32(uint32_t saddr, int rank, float v) {
    uint32_t rem;
    asm volatile("mapa.shared::cluster.u32 %0, %1, %2;" : "=r"(rem) : "r"(saddr), "r"(rank));
    asm volatile("st.shared::cluster.f32 [%0], %1;" :: "r"(rem), "f"(v) : "memory");
}
#define CLUSTER_ARRIVE() asm volatile("barrier.cluster.arrive.aligned;" ::: "memory")
#define CLUSTER_WAIT()   asm volatile("barrier.cluster.wait.aligned;" ::: "memory")

// ---------------- xp GEMM: out[m,g] = X[m,:] . W[g,:] + (bi[g]+bh[g]) ----------------
__global__ __launch_bounds__(256) void gemm_xp(const float* __restrict__ xin,
                                               const float* __restrict__ Wih,
                                               const float* __restrict__ bih,
                                               const float* __restrict__ bhh,
                                               int layer)
{
    const float* X  = layer ? g_y0 : xin;
    const float* W  = Wih + (size_t)layer * G4 * Hh;
    const float* b1 = bih + layer * G4;
    const float* b2 = bhh + layer * G4;

    __shared__ float As[32][68];
    __shared__ float Bs[32][132];

    const int tid = threadIdx.x;
    const int tx = tid & 15, ty = tid >> 4;
    const int m0 = blockIdx.y * 64;
    const int n0 = blockIdx.x * 128;

    ull acc[4][4];
#pragma unroll
    for (int i = 0; i < 4; i++)
#pragma unroll
        for (int j = 0; j < 4; j++) acc[i][j] = 0ull;

    for (int k0 = 0; k0 < Hh; k0 += 32) {
#pragma unroll
        for (int r = 0; r < 2; r++) {
            int i = tid + r * 256;
            int row = i >> 3, kq = i & 7;
            float4 v = *(const float4*)&X[(size_t)(m0 + row) * Hh + k0 + kq * 4];
            As[kq * 4 + 0][row] = v.x; As[kq * 4 + 1][row] = v.y;
            As[kq * 4 + 2][row] = v.z; As[kq * 4 + 3][row] = v.w;
        }
#pragma unroll
        for (int r = 0; r < 4; r++) {
            int i = tid + r * 256;
            int row = i >> 3, kq = i & 7;
            float4 v = *(const float4*)&W[(size_t)(n0 + row) * Hh + k0 + kq * 4];
            Bs[kq * 4 + 0][row] = v.x; Bs[kq * 4 + 1][row] = v.y;
            Bs[kq * 4 + 2][row] = v.z; Bs[kq * 4 + 3][row] = v.w;
        }
        __syncthreads();

#pragma unroll
        for (int kk = 0; kk < 32; kk++) {
            float4 a4 = *(const float4*)&As[kk][ty * 4];
            ull aa0 = pack2(a4.x, a4.x), aa1 = pack2(a4.y, a4.y);
            ull aa2 = pack2(a4.z, a4.z), aa3 = pack2(a4.w, a4.w);
            ulonglong2 bA = *(const ulonglong2*)&Bs[kk][tx * 4];
            ulonglong2 bB = *(const ulonglong2*)&Bs[kk][64 + tx * 4];
            fma2(acc[0][0], aa0, bA.x); fma2(acc[0][1], aa0, bA.y);
            fma2(acc[0][2], aa0, bB.x); fma2(acc[0][3], aa0, bB.y);
            fma2(acc[1][0], aa1, bA.x); fma2(acc[1][1], aa1, bA.y);
            fma2(acc[1][2], aa1, bB.x); fma2(acc[1][3], aa1, bB.y);
            fma2(acc[2][0], aa2, bA.x); fma2(acc[2][1], aa2, bA.y);
            fma2(acc[2][2], aa2, bB.x); fma2(acc[2][3], aa2, bB.y);
            fma2(acc[3][0], aa3, bA.x); fma2(acc[3][1], aa3, bA.y);
            fma2(acc[3][2], aa3, bB.x); fma2(acc[3][3], aa3, bB.y);
        }
        __syncthreads();
    }

    const int n1 = n0 + tx * 4;
    const int n2 = n0 + 64 + tx * 4;
    float4 bb1 = *(const float4*)&b1[n1];
    float4 bc1 = *(const float4*)&b2[n1];
    float4 bb2 = *(const float4*)&b1[n2];
    float4 bc2 = *(const float4*)&b2[n2];
    bb1.x += bc1.x; bb1.y += bc1.y; bb1.z += bc1.z; bb1.w += bc1.w;
    bb2.x += bc2.x; bb2.y += bc2.y; bb2.z += bc2.z; bb2.w += bc2.w;

#pragma unroll
    for (int i = 0; i < 4; i++) {
        float4 o1, o2;
        unpack2(acc[i][0], o1.x, o1.y);
        unpack2(acc[i][1], o1.z, o1.w);
        unpack2(acc[i][2], o2.x, o2.y);
        unpack2(acc[i][3], o2.z, o2.w);
        o1.x += bb1.x; o1.y += bb1.y; o1.z += bb1.z; o1.w += bb1.w;
        o2.x += bb2.x; o2.y += bb2.y; o2.z += bb2.z; o2.w += bb2.w;
        int m = m0 + ty * 4 + i;
        *(float4*)&g_xp[(size_t)m * G4 + n1] = o1;
        *(float4*)&g_xp[(size_t)m * G4 + n2] = o2;
    }
}

// ---------------- clustered LSTM recurrence ----------------
// One batch per 4-CTA cluster. CTA rank r owns n in [64r, 64r+64) for all 4 gates
// (256 gate rows). Wh rows live in REGISTERS as bf16x2 (128 regs/thread, zero
// per-step weight traffic). h (256 fp32) double-buffered in SMEM, replicated per
// CTA; cell update pushes 64 new h values to all 4 cluster CTAs via DSMEM, then
// barrier.cluster synchronizes the step.
__global__ __launch_bounds__(256, 1) __cluster_dims__(CL, 1, 1)
void lstm_rec(const float* __restrict__ Whh,
              float* __restrict__ yout,
              float* __restrict__ hT,
              float* __restrict__ cT,
              int layer)
{
    __shared__ __align__(16) float h_s[2][Hh];
    __shared__ float red[4][64];

    const int tid = threadIdx.x;
    uint32_t rank;
    asm("mov.u32 %0, %%cluster_ctarank;" : "=r"(rank));
    const int b  = blockIdx.x / CL;
    const int n0 = (int)rank * 64;

    const int gate = tid >> 6;           // 0..3
    const int nl   = tid & 63;           // 0..63
    const int G    = gate * 256 + n0 + nl;

    // ---- load this thread's Wh row into registers as bf16x2 (one-time) ----
    const float4* Wrow = (const float4*)(Whh + (size_t)layer * G4 * Hh + (size_t)G * Hh);
    unsigned wreg[128];
#pragma unroll
    for (int q = 0; q < 64; q++) {
        float4 v = __ldg(&Wrow[q]);
        wreg[2 * q + 0] = pack_bf16x2(v.x, v.y);
        wreg[2 * q + 1] = pack_bf16x2(v.z, v.w);
    }

    // zero h buffer 0 (buffer 1 is fully overwritten by step-0 pushes)
    for (int i = tid; i < Hh; i += 256) h_s[0][i] = 0.0f;
    __syncthreads();
    CLUSTER_ARRIVE();
    CLUSTER_WAIT();

    const float* xp = g_xp + (size_t)b * Ss * G4 + G;
    float* y = layer ? yout : g_y0;

    float c_reg = 0.0f;                      // valid in tid<64 only
    const uint32_t hbase0 = smem_u32(&h_s[0][0]);
    const uint32_t hbase1 = smem_u32(&h_s[1][0]);

    float xpv = __ldg(&xp[0]);

    for (int t = 0; t < Ss; t++) {
        // prefetch next step's xp (overlaps with the dot)
        float xpn = __ldg(&xp[(size_t)(t + 1 < Ss ? t + 1 : t) * G4]);

        // ---- dot: gates[G] = sum_k Wh[G,k] * h[k]  (K=256, f32x2) ----
        const ulonglong2* hv = (const ulonglong2*)&h_s[t & 1][0];
        ull acc0 = 0ull, acc1 = 0ull;
#pragma unroll
        for (int q = 0; q < 64; q++) {
            ulonglong2 hh = hv[q];                   // pairs 2q, 2q+1 (broadcast)
            fma2(acc0, hh.x, expand_bf16x2(wreg[2 * q + 0]));
            fma2(acc1, hh.y, expand_bf16x2(wreg[2 * q + 1]));
        }
        float s0, s1, s2, s3;
        unpack2(acc0, s0, s1);
        unpack2(acc1, s2, s3);
        red[gate][nl] = ((s0 + s2) + (s1 + s3)) + xpv;
        __syncthreads();

        // ---- cell update for the 64 n's this CTA owns ----
        if (tid < 64) {
            float iv = red[0][tid];
            float fv = red[1][tid];
            float gv = red[2][tid];
            float ov = red[3][tid];
            float c  = sig_f(fv) * c_reg + sig_f(iv) * tanh_f(gv);
            float h  = sig_f(ov) * tanh_f(c);
            c_reg = c;
            int n = n0 + tid;
            // push h to all 4 cluster CTAs' next-h buffer (incl. self)
            uint32_t dst = ((t & 1) ? hbase0 : hbase1) + (uint32_t)n * 4u;
#pragma unroll
            for (int p = 0; p < CL; p++) st_cluster_f32(dst, p, h);
            y[(size_t)b * Ss * Hh + (size_t)t * Hh + n] = h;
            if (t == Ss - 1) { hT[b * Hh + n] = h; cT[b * Hh + n] = c; }
        }
        xpv = xpn;
        CLUSTER_ARRIVE();   // release: DSMEM h pushes visible after peers' wait
        CLUSTER_WAIT();
    }
}

// ---------------- launch ----------------
extern "C" void kernel_launch(void* const* d_in, const int* in_sizes, int n_in,
                              void* d_out, int out_size)
{
    (void)in_sizes; (void)n_in; (void)out_size;
    const float* x    = (const float*)d_in[0];   // [B,S,H]
    const float* Wih  = (const float*)d_in[1];   // [L,4H,H]
    const float* bih  = (const float*)d_in[2];   // [L,4H]
    const float* Whh  = (const float*)d_in[3];   // [L,4H,H]
    const float* bhh  = (const float*)d_in[4];   // [L,4H]

    float* out = (float*)d_out;
    float* y_x = out;                                   // [B,S,H]
    float* hT  = out + (size_t)Bb * Ss * Hh;            // [L,B,H]
    float* cT  = hT + (size_t)Ll * Bb * Hh;             // [L,B,H]

    dim3 ggrid(G4 / 128, (Bb * Ss) / 64);

    for (int layer = 0; layer < Ll; layer++) {
        gemm_xp<<<ggrid, 256>>>(x, Wih, bih, bhh, layer);
        lstm_rec<<<NCTA, 256>>>(Whh, y_x,
                                hT + (size_t)layer * Bb * Hh,
                                cT + (size_t)layer * Bb * Hh,
                                layer);
    }
}

// round 4
// speedup vs baseline: 6.7439x; 1.1343x over previous
#include <cuda_runtime.h>
#include <cuda_bf16.h>
#include <math.h>
#include <stdint.h>

#define Bb   32
#define Ss   2048
#define Hh   256
#define G4   1024
#define Ll   2
#define CL   4
#define NCTA (Bb * CL)

// ---------------- device scratch ----------------
__device__ float g_xp[(size_t)Bb * Ss * G4];                 // 256 MB
__device__ float g_y0[(size_t)Bb * Ss * Hh];                 // 64 MB
__device__ __nv_bfloat16 g_ah[(size_t)Bb * Ss * Hh];         // X hi (bf16)
__device__ __nv_bfloat16 g_al[(size_t)Bb * Ss * Hh];         // X lo
__device__ __nv_bfloat16 g_bh[(size_t)G4 * Hh];              // W hi
__device__ __nv_bfloat16 g_bl[(size_t)G4 * Hh];              // W lo

// ---------------- helpers ----------------
typedef unsigned long long ull;
__device__ __forceinline__ void unpack2(ull v, float& lo, float& hi) {
    asm("mov.b64 {%0,%1},%2;" : "=f"(lo), "=f"(hi) : "l"(v));
}
__device__ __forceinline__ void fma2(ull& acc, ull a, ull b) {
    asm("fma.rn.f32x2 %0,%1,%2,%0;" : "+l"(acc) : "l"(a), "l"(b));
}
__device__ __forceinline__ unsigned pack_bf16x2(float lo, float hi) {
    unsigned d;
    asm("cvt.rn.bf16x2.f32 %0, %1, %2;" : "=r"(d) : "f"(hi), "f"(lo));
    return d;
}
__device__ __forceinline__ ull expand_a(unsigned w) {
    unsigned lo, hi;
    asm("shl.b32 %0, %1, 16;" : "=r"(lo) : "r"(w));
    asm("and.b32 %0, %1, 0xFFFF0000;" : "=r"(hi) : "r"(w));
    ull r; asm("mov.b64 %0,{%1,%2};" : "=l"(r) : "r"(lo), "r"(hi));
    return r;
}
__device__ __forceinline__ ull expand_b(unsigned w) {
    unsigned lo, hi;
    asm("mul.lo.s32 %0, %1, 65536;" : "=r"(lo) : "r"(w));
    asm("and.b32 %0, %1, 0xFFFF0000;" : "=r"(hi) : "r"(w));
    ull r; asm("mov.b64 %0,{%1,%2};" : "=l"(r) : "r"(lo), "r"(hi));
    return r;
}
__device__ __forceinline__ float tanh_f(float x) {
    float y; asm("tanh.approx.f32 %0,%1;" : "=f"(y) : "f"(x)); return y;
}
__device__ __forceinline__ float sig_f(float x) {
    return fmaf(0.5f, tanh_f(0.5f * x), 0.5f);
}
__device__ __forceinline__ uint32_t smem_u32(const void* p) {
    uint32_t a;
    asm("{ .reg .u64 t; cvta.to.shared.u64 t, %1; cvt.u32.u64 %0, t; }" : "=r"(a) : "l"(p));
    return a;
}
__device__ __forceinline__ void st_cluster_f32(uint32_t saddr, int rank, float v) {
    uint32_t rem;
    asm volatile("mapa.shared::cluster.u32 %0, %1, %2;" : "=r"(rem) : "r"(saddr), "r"(rank));
    asm volatile("st.shared::cluster.f32 [%0], %1;" :: "r"(rem), "f"(v) : "memory");
}
#define CLUSTER_ARRIVE() asm volatile("barrier.cluster.arrive.aligned;" ::: "memory")
#define CLUSTER_WAIT()   asm volatile("barrier.cluster.wait.aligned;" ::: "memory")

__device__ __forceinline__ void ldsm4(uint32_t& r0, uint32_t& r1, uint32_t& r2, uint32_t& r3,
                                      uint32_t addr) {
    asm volatile("ldmatrix.sync.aligned.m8n8.x4.shared.b16 {%0,%1,%2,%3}, [%4];"
                 : "=r"(r0), "=r"(r1), "=r"(r2), "=r"(r3) : "r"(addr));
}
__device__ __forceinline__ void mma16816(float* c, uint32_t a0, uint32_t a1, uint32_t a2,
                                         uint32_t a3, uint32_t b0, uint32_t b1) {
    asm volatile(
        "mma.sync.aligned.m16n8k16.row.col.f32.bf16.bf16.f32 "
        "{%0,%1,%2,%3}, {%4,%5,%6,%7}, {%8,%9}, {%0,%1,%2,%3};"
        : "+f"(c[0]), "+f"(c[1]), "+f"(c[2]), "+f"(c[3])
        : "r"(a0), "r"(a1), "r"(a2), "r"(a3), "r"(b0), "r"(b1));
}

// ---------------- split kernel: f32 -> bf16 hi + bf16 lo ----------------
__global__ __launch_bounds__(256) void conv_split(const float* __restrict__ src,
                                                  __nv_bfloat16* __restrict__ hi,
                                                  __nv_bfloat16* __restrict__ lo,
                                                  int n4)
{
    int i = blockIdx.x * blockDim.x + threadIdx.x;
    if (i >= n4) return;
    float4 v = ((const float4*)src)[i];
    __nv_bfloat16 h0 = __float2bfloat16(v.x);
    __nv_bfloat16 h1 = __float2bfloat16(v.y);
    __nv_bfloat16 h2 = __float2bfloat16(v.z);
    __nv_bfloat16 h3 = __float2bfloat16(v.w);
    __nv_bfloat16 l0 = __float2bfloat16(v.x - __bfloat162float(h0));
    __nv_bfloat16 l1 = __float2bfloat16(v.y - __bfloat162float(h1));
    __nv_bfloat16 l2 = __float2bfloat16(v.z - __bfloat162float(h2));
    __nv_bfloat16 l3 = __float2bfloat16(v.w - __bfloat162float(h3));
    ((__nv_bfloat162*)hi)[2 * i + 0] = __nv_bfloat162(h0, h1);
    ((__nv_bfloat162*)hi)[2 * i + 1] = __nv_bfloat162(h2, h3);
    ((__nv_bfloat162*)lo)[2 * i + 0] = __nv_bfloat162(l0, l1);
    ((__nv_bfloat162*)lo)[2 * i + 1] = __nv_bfloat162(l2, l3);
}

// ---------------- warp-MMA GEMM: g_xp[m,g] = X[m,:].W[g,:] + (b1+b2)[g] ----------------
// Split-precision bf16 (XhWh + XhWl + XlWh), fp32 accum, mma.sync m16n8k16.
// CTA tile 128x128, 8 warps in 4(m) x 2(n), warp tile 32x64. K chunks of 64.
#define KSTR 72   // smem row stride in halves (144 B -> conflict-free ldmatrix)

static constexpr int SMB_AH = 0;
static constexpr int SMB_AL = SMB_AH + 128 * KSTR * 2;
static constexpr int SMB_BH = SMB_AL + 128 * KSTR * 2;
static constexpr int SMB_BL = SMB_BH + 128 * KSTR * 2;
static constexpr int SMB_BIAS = SMB_BL + 128 * KSTR * 2;
static constexpr int SMB_TOT = SMB_BIAS + 128 * 4;

__global__ __launch_bounds__(256, 1) void gemm_bf16mma(const float* __restrict__ b1g,
                                                       const float* __restrict__ b2g,
                                                       int layer)
{
    extern __shared__ char smem[];
    const uint32_t sb = smem_u32(smem);
    const int tid = threadIdx.x;
    const int lane = tid & 31;
    const int w = tid >> 5;
    const int wm = (w & 3) * 32;       // warp m-offset in CTA tile
    const int wn = (w >> 2) * 64;      // warp n-offset
    const int m0 = blockIdx.y * 128;
    const int n0 = blockIdx.x * 128;

    // bias into smem
    if (tid < 128) {
        ((float*)(smem + SMB_BIAS))[tid] =
            b1g[layer * G4 + n0 + tid] + b2g[layer * G4 + n0 + tid];
    }

    const uint4* Ah = (const uint4*)g_ah;
    const uint4* Al = (const uint4*)g_al;
    const uint4* Bh = (const uint4*)g_bh;
    const uint4* Bl = (const uint4*)g_bl;

    float acc[2][8][4];
#pragma unroll
    for (int i = 0; i < 2; i++)
#pragma unroll
        for (int j = 0; j < 8; j++)
#pragma unroll
            for (int k = 0; k < 4; k++) acc[i][j][k] = 0.0f;

    // per-lane ldmatrix addresses (row part)
    const int a_row = (lane & 15);              // + warp m + mt*16
    const int a_kof = (lane >> 4) << 3;         // 0 or 8 halves
    const int b_row = (lane & 7) + ((lane >> 4) << 3);   // + warp n + pair*16
    const int b_kof = ((lane >> 3) & 1) << 3;

    for (int kc = 0; kc < 4; kc++) {
        // stage 4 tiles of [128 rows][64 halves] (8 uint4/row)
#pragma unroll
        for (int r = 0; r < 4; r++) {
            int i = tid + r * 256;
            int row = i >> 3, c8 = i & 7;
            uint32_t dst = (uint32_t)(row * KSTR * 2 + c8 * 16);
            int gaix = (m0 + row) * 32 + kc * 8 + c8;
            int gbix = (n0 + row) * 32 + kc * 8 + c8;
            *(uint4*)(smem + SMB_AH + dst) = Ah[gaix];
            *(uint4*)(smem + SMB_AL + dst) = Al[gaix];
            *(uint4*)(smem + SMB_BH + dst) = Bh[gbix];
            *(uint4*)(smem + SMB_BL + dst) = Bl[gbix];
        }
        __syncthreads();

#pragma unroll
        for (int ks = 0; ks < 4; ks++) {
            const int kh = ks * 16;
            // A fragments: 2 m-tiles, hi & lo
            uint32_t ah[2][4], al[2][4];
#pragma unroll
            for (int mt = 0; mt < 2; mt++) {
                uint32_t off = (uint32_t)(((wm + mt * 16 + a_row) * KSTR + kh + a_kof) * 2);
                ldsm4(ah[mt][0], ah[mt][1], ah[mt][2], ah[mt][3], sb + SMB_AH + off);
                ldsm4(al[mt][0], al[mt][1], al[mt][2], al[mt][3], sb + SMB_AL + off);
            }
            // B fragments: 4 n16-pairs, hi & lo
            uint32_t bh[4][4], bl[4][4];
#pragma unroll
            for (int p = 0; p < 4; p++) {
                uint32_t off = (uint32_t)(((wn + p * 16 + b_row) * KSTR + kh + b_kof) * 2);
                ldsm4(bh[p][0], bh[p][1], bh[p][2], bh[p][3], sb + SMB_BH + off);
                ldsm4(bl[p][0], bl[p][1], bl[p][2], bl[p][3], sb + SMB_BL + off);
            }
#pragma unroll
            for (int mt = 0; mt < 2; mt++) {
#pragma unroll
                for (int p = 0; p < 4; p++) {
                    // n-tile 2p   : regs bh[p][0..1]
                    mma16816(acc[mt][2 * p + 0], ah[mt][0], ah[mt][1], ah[mt][2], ah[mt][3],
                             bh[p][0], bh[p][1]);
                    mma16816(acc[mt][2 * p + 0], ah[mt][0], ah[mt][1], ah[mt][2], ah[mt][3],
                             bl[p][0], bl[p][1]);
                    mma16816(acc[mt][2 * p + 0], al[mt][0], al[mt][1], al[mt][2], al[mt][3],
                             bh[p][0], bh[p][1]);
                    // n-tile 2p+1 : regs bh[p][2..3]
                    mma16816(acc[mt][2 * p + 1], ah[mt][0], ah[mt][1], ah[mt][2], ah[mt][3],
                             bh[p][2], bh[p][3]);
                    mma16816(acc[mt][2 * p + 1], ah[mt][0], ah[mt][1], ah[mt][2], ah[mt][3],
                             bl[p][2], bl[p][3]);
                    mma16816(acc[mt][2 * p + 1], al[mt][0], al[mt][1], al[mt][2], al[mt][3],
                             bh[p][2], bh[p][3]);
                }
            }
        }
        __syncthreads();
    }

    // epilogue: acc tile (mt,nt) element (groupID, 2*tig) etc.
    const float* bias = (const float*)(smem + SMB_BIAS);
    const int gid = lane >> 2;
    const int tig = lane & 3;
#pragma unroll
    for (int mt = 0; mt < 2; mt++) {
#pragma unroll
        for (int nt = 0; nt < 8; nt++) {
            int col = wn + nt * 8 + tig * 2;
            float b0 = bias[col], b1 = bias[col + 1];
            int gm0 = m0 + wm + mt * 16 + gid;
            float* p0 = &g_xp[(size_t)gm0 * G4 + n0 + col];
            float* p1 = &g_xp[(size_t)(gm0 + 8) * G4 + n0 + col];
            float2 v0 = { acc[mt][nt][0] + b0, acc[mt][nt][1] + b1 };
            float2 v1 = { acc[mt][nt][2] + b0, acc[mt][nt][3] + b1 };
            *(float2*)p0 = v0;
            *(float2*)p1 = v1;
        }
    }
}

// ---------------- clustered LSTM recurrence ----------------
__global__ __launch_bounds__(256, 1) __cluster_dims__(CL, 1, 1)
void lstm_rec(const float* __restrict__ Whh,
              float* __restrict__ yout,
              float* __restrict__ hT,
              float* __restrict__ cT,
              int layer)
{
    __shared__ __align__(16) float h_s[2][Hh];
    __shared__ float red[4][64];

    const int tid = threadIdx.x;
    uint32_t rank;
    asm("mov.u32 %0, %%cluster_ctarank;" : "=r"(rank));
    const int b  = blockIdx.x / CL;
    const int n0 = (int)rank * 64;

    const int gate = tid >> 6;
    const int nl   = tid & 63;
    const int G    = gate * 256 + n0 + nl;

    const float4* Wrow = (const float4*)(Whh + (size_t)layer * G4 * Hh + (size_t)G * Hh);
    unsigned wreg[128];
#pragma unroll
    for (int q = 0; q < 64; q++) {
        float4 v = __ldg(&Wrow[q]);
        wreg[2 * q + 0] = pack_bf16x2(v.x, v.y);
        wreg[2 * q + 1] = pack_bf16x2(v.z, v.w);
    }

    for (int i = tid; i < Hh; i += 256) h_s[0][i] = 0.0f;
    __syncthreads();
    CLUSTER_ARRIVE();
    CLUSTER_WAIT();

    const float* xp = g_xp + (size_t)b * Ss * G4 + G;
    float* y = layer ? yout : g_y0;

    float c_reg = 0.0f;
    const uint32_t hbase0 = smem_u32(&h_s[0][0]);
    const uint32_t hbase1 = smem_u32(&h_s[1][0]);

    float xpv = __ldg(&xp[0]);

    for (int t = 0; t < Ss; t++) {
        float xpn = __ldg(&xp[(size_t)(t + 1 < Ss ? t + 1 : t) * G4]);

        const ulonglong2* hv = (const ulonglong2*)&h_s[t & 1][0];
        ull acc0 = 0ull, acc1 = 0ull;
#pragma unroll
        for (int q = 0; q < 64; q++) {
            ulonglong2 hh = hv[q];
            fma2(acc0, hh.x, expand_a(wreg[2 * q + 0]));
            fma2(acc1, hh.y, expand_b(wreg[2 * q + 1]));
        }
        float s0, s1, s2, s3;
        unpack2(acc0, s0, s1);
        unpack2(acc1, s2, s3);
        red[gate][nl] = ((s0 + s2) + (s1 + s3)) + xpv;
        __syncthreads();

        if (tid < 64) {
            float iv = red[0][tid];
            float fv = red[1][tid];
            float gv = red[2][tid];
            float ov = red[3][tid];
            float c  = sig_f(fv) * c_reg + sig_f(iv) * tanh_f(gv);
            float h  = sig_f(ov) * tanh_f(c);
            c_reg = c;
            int n = n0 + tid;
            uint32_t dst = ((t & 1) ? hbase0 : hbase1) + (uint32_t)n * 4u;
#pragma unroll
            for (int p = 0; p < CL; p++) st_cluster_f32(dst, p, h);
            y[(size_t)b * Ss * Hh + (size_t)t * Hh + n] = h;
            if (t == Ss - 1) { hT[b * Hh + n] = h; cT[b * Hh + n] = c; }
        }
        xpv = xpn;
        CLUSTER_ARRIVE();
        CLUSTER_WAIT();
    }
}

// ---------------- launch ----------------
extern "C" void kernel_launch(void* const* d_in, const int* in_sizes, int n_in,
                              void* d_out, int out_size)
{
    (void)in_sizes; (void)n_in; (void)out_size;
    const float* x    = (const float*)d_in[0];   // [B,S,H]
    const float* Wih  = (const float*)d_in[1];   // [L,4H,H]
    const float* bih  = (const float*)d_in[2];   // [L,4H]
    const float* Whh  = (const float*)d_in[3];   // [L,4H,H]
    const float* bhh  = (const float*)d_in[4];   // [L,4H]

    float* out = (float*)d_out;
    float* y_x = out;
    float* hT  = out + (size_t)Bb * Ss * Hh;
    float* cT  = hT + (size_t)Ll * Bb * Hh;

    cudaFuncSetAttribute(gemm_bf16mma, cudaFuncAttributeMaxDynamicSharedMemorySize, SMB_TOT);

    __nv_bfloat16 *ah, *al, *bh, *bl;
    cudaGetSymbolAddress((void**)&ah, g_ah);
    cudaGetSymbolAddress((void**)&al, g_al);
    cudaGetSymbolAddress((void**)&bh, g_bh);
    cudaGetSymbolAddress((void**)&bl, g_bl);
    float* y0;
    cudaGetSymbolAddress((void**)&y0, g_y0);

    const int nX4 = (Bb * Ss * Hh) / 4;
    const int nW4 = (G4 * Hh) / 4;

    dim3 ggrid(G4 / 128, (Bb * Ss) / 128);

    for (int layer = 0; layer < Ll; layer++) {
        const float* xin = layer ? (const float*)y0 : x;
        conv_split<<<nX4 / 256, 256>>>(xin, ah, al, nX4);
        conv_split<<<nW4 / 256, 256>>>(Wih + (size_t)layer * G4 * Hh, bh, bl, nW4);
        gemm_bf16mma<<<ggrid, 256, SMB_TOT>>>(bih, bhh, layer);
        lstm_rec<<<NCTA, 256>>>(Whh, y_x,
                                hT + (size_t)layer * Bb * Hh,
                                cT + (size_t)layer * Bb * Hh,
                                layer);
    }
}